// round 9
// baseline (speedup 1.0000x reference)
#include <cuda_runtime.h>
#include <cuda_bf16.h>
#include <cuda_fp16.h>
#include <cstdint>

#define IN_F      256
#define OUT_F     256
#define OUTSTRIDE 512
#define MAXE      3200000
#define MAXM      100000
#define NB        100352          // 392 * 256 bins (>= N_NODES)

// ---------------- device scratch (allocation-free rule) ---------------------
__device__ __nv_bfloat16 g_Whi[OUT_F * IN_F];   // transposed: [n][k]
__device__ __nv_bfloat16 g_Wlo[OUT_F * IN_F];
__device__ __half        g_ftH[(size_t)MAXM * OUT_F];  // fp16 mirror of ft_input
__device__ int2          g_pack[MAXE];          // {src, val_bits}, sorted by dst
__device__ int           g_hist[NB];
__device__ int           g_offs[NB];
__device__ int           g_bsum[512];
__device__ unsigned      g_idx_is64;

// ---------------- helpers ---------------------------------------------------
static __device__ __forceinline__ uint32_t smem_u32(const void* p) {
    uint32_t a;
    asm("{ .reg .u64 t; cvta.to.shared.u64 t, %1; cvt.u32.u64 %0, t; }"
        : "=r"(a) : "l"(p));
    return a;
}
static __device__ __forceinline__ void ldsm4(uint32_t* r, uint32_t addr) {
    asm volatile("ldmatrix.sync.aligned.m8n8.x4.shared.b16 {%0,%1,%2,%3}, [%4];"
                 : "=r"(r[0]), "=r"(r[1]), "=r"(r[2]), "=r"(r[3]) : "r"(addr));
}
static __device__ __forceinline__ void mma16816(float* c, const uint32_t* a,
                                                const uint32_t* b) {
    asm volatile(
        "mma.sync.aligned.m16n8k16.row.col.f32.bf16.bf16.f32 "
        "{%0,%1,%2,%3}, {%4,%5,%6,%7}, {%8,%9}, {%0,%1,%2,%3};"
        : "+f"(c[0]), "+f"(c[1]), "+f"(c[2]), "+f"(c[3])
        : "r"(a[0]), "r"(a[1]), "r"(a[2]), "r"(a[3]), "r"(b[0]), "r"(b[1]));
}
static __device__ __forceinline__ uint32_t pack2(__nv_bfloat16 a, __nv_bfloat16 b) {
    return ((uint32_t)__bfloat16_as_ushort(b) << 16) | __bfloat16_as_ushort(a);
}
// block-wide inclusive scan (blockDim multiple of 32, <= 1024)
static __device__ __forceinline__ int block_incl_scan(int v, int* shWarp) {
    const int lane = threadIdx.x & 31, w = threadIdx.x >> 5;
#pragma unroll
    for (int o = 1; o < 32; o <<= 1) {
        int t = __shfl_up_sync(0xffffffffu, v, o);
        if (lane >= o) v += t;
    }
    if (lane == 31) shWarp[w] = v;
    __syncthreads();
    if (w == 0) {
        const int nw = blockDim.x >> 5;
        int s = (lane < nw) ? shWarp[lane] : 0;
#pragma unroll
        for (int o = 1; o < 32; o <<= 1) {
            int t = __shfl_up_sync(0xffffffffu, s, o);
            if (lane >= o) s += t;
        }
        if (lane < nw) shWarp[lane] = s;
    }
    __syncthreads();
    if (w > 0) v += shWarp[w - 1];
    return v;
}

// ---------------------------------------------------------------------------
__global__ void detect_idx_kernel(const unsigned* __restrict__ p) {
    unsigned v = p[2 * threadIdx.x + 1];
    int any = __syncthreads_or(v != 0u);
    if (threadIdx.x == 0) g_idx_is64 = any ? 0u : 1u;
}

__global__ void zero_hist_kernel() {
    g_hist[blockIdx.x * 256 + threadIdx.x] = 0;
}

// W[k][n] -> transposed bf16 hi/lo: g_W{hi,lo}[n][k].
__global__ void conv_w_kernel(const float* __restrict__ W) {
    int i = blockIdx.x * blockDim.x + threadIdx.x;   // 65536
    int k = i >> 8, n = i & 255;
    float x = W[i];
    __nv_bfloat16 h = __float2bfloat16_rn(x);
    g_Whi[n * IN_F + k] = h;
    g_Wlo[n * IN_F + k] = __float2bfloat16_rn(x - __bfloat162float(h));
}

// ---------------------------------------------------------------------------
// Counting sort by dst: histogram -> scan -> scatter into 8B records.
// After sort_pack_kernel, g_offs[d] = END offset of d's run; start = end-hist.
// ---------------------------------------------------------------------------
__global__ void hist_kernel(const void* __restrict__ edst, int E) {
    int i = blockIdx.x * blockDim.x + threadIdx.x;
    if (i >= E) return;
    int d = g_idx_is64 ? (int)__ldg((const long long*)edst + i)
                       : __ldg((const int*)edst + i);
    atomicAdd(&g_hist[d], 1);
}
__global__ void scanA_kernel() {            // grid 392, block 256
    __shared__ int shW[8];
    int i = blockIdx.x * 256 + threadIdx.x;
    int v = g_hist[i];
    int inc = block_incl_scan(v, shW);
    g_offs[i] = inc - v;
    if (threadIdx.x == 255) g_bsum[blockIdx.x] = inc;
}
__global__ void scanB_kernel() {            // grid 1, block 512
    __shared__ int shW[16];
    int t = threadIdx.x;
    int v = (t < 392) ? g_bsum[t] : 0;
    int inc = block_incl_scan(v, shW);
    if (t < 392) g_bsum[t] = inc - v;
}
__global__ void scanC_kernel() {            // grid 392, block 256
    g_offs[blockIdx.x * 256 + threadIdx.x] += g_bsum[blockIdx.x];
}
__global__ void sort_pack_kernel(const void* __restrict__ esrc,
                                 const void* __restrict__ edst,
                                 const float* __restrict__ ev, int E) {
    int i = blockIdx.x * blockDim.x + threadIdx.x;
    if (i >= E) return;
    int s, d;
    if (g_idx_is64) {
        s = (int)__ldg((const long long*)esrc + i);
        d = (int)__ldg((const long long*)edst + i);
    } else {
        s = __ldg((const int*)esrc + i);
        d = __ldg((const int*)edst + i);
    }
    int pos = atomicAdd(&g_offs[d], 1);
    g_pack[pos] = make_int2(s, __float_as_int(__ldg(ev + i)));
}

// ---------------------------------------------------------------------------
// GEMM via mma.sync (HMMA.16816 bf16), split-bf16 3-product.
// Block 128x128, 8 warps (warp tile 32x64), K-chunk 32, K=256.
// bnBase selects the N-half. Epilogue writes fp32 out AND fp16 mirror g_ftH.
// ---------------------------------------------------------------------------
#define SSTR 40

__global__ __launch_bounds__(256)
void gemm_mma_kernel(const float* __restrict__ X, float* __restrict__ out,
                     int M, int bnBase) {
    __shared__ __align__(16) __nv_bfloat16 sAhi[128 * SSTR];
    __shared__ __align__(16) __nv_bfloat16 sAlo[128 * SSTR];
    __shared__ __align__(16) __nv_bfloat16 sBhi[128 * SSTR];
    __shared__ __align__(16) __nv_bfloat16 sBlo[128 * SSTR];

    const int tid  = threadIdx.x;
    const int lane = tid & 31, wid = tid >> 5;
    const int bm = blockIdx.x * 128;
    const int bn = bnBase;
    const int wm = (wid & 3) * 32;
    const int wn = (wid >> 2) * 64;

    float acc[2][8][4];
#pragma unroll
    for (int i = 0; i < 2; i++)
#pragma unroll
        for (int j = 0; j < 8; j++)
#pragma unroll
            for (int k = 0; k < 4; k++) acc[i][j][k] = 0.f;

    const int rA = ((lane >> 3) & 1) * 8 + (lane & 7);
    const int kA = (lane >> 4) * 8;
    const int rB = (lane >> 4) * 8 + (lane & 7);
    const int kB = ((lane >> 3) & 1) * 8;

    const uint32_t aHiB = smem_u32(sAhi), aLoB = smem_u32(sAlo);
    const uint32_t bHiB = smem_u32(sBhi), bLoB = smem_u32(sBlo);

    for (int kc = 0; kc < 8; kc++) {
        const int k0 = kc * 32;
        __syncthreads();
#pragma unroll
        for (int i = 0; i < 4; i++) {
            int idx = tid + i * 256;
            int row = idx >> 3, c = idx & 7;
            float4 v = make_float4(0.f, 0.f, 0.f, 0.f);
            if (bm + row < M)
                v = __ldg(reinterpret_cast<const float4*>(
                        X + (size_t)(bm + row) * IN_F + k0 + c * 4));
            __nv_bfloat16 h0 = __float2bfloat16_rn(v.x);
            __nv_bfloat16 h1 = __float2bfloat16_rn(v.y);
            __nv_bfloat16 h2 = __float2bfloat16_rn(v.z);
            __nv_bfloat16 h3 = __float2bfloat16_rn(v.w);
            uint2 ph = make_uint2(pack2(h0, h1), pack2(h2, h3));
            uint2 pl = make_uint2(
                pack2(__float2bfloat16_rn(v.x - __bfloat162float(h0)),
                      __float2bfloat16_rn(v.y - __bfloat162float(h1))),
                pack2(__float2bfloat16_rn(v.z - __bfloat162float(h2)),
                      __float2bfloat16_rn(v.w - __bfloat162float(h3))));
            *reinterpret_cast<uint2*>(&sAhi[row * SSTR + c * 4]) = ph;
            *reinterpret_cast<uint2*>(&sAlo[row * SSTR + c * 4]) = pl;
        }
#pragma unroll
        for (int i = 0; i < 4; i++) {
            int idx = tid + i * 256;
            int row = idx >> 3, c = idx & 7;
            *reinterpret_cast<uint2*>(&sBhi[row * SSTR + c * 4]) =
                __ldg(reinterpret_cast<const uint2*>(
                    g_Whi + (size_t)(bn + row) * IN_F + k0 + c * 4));
            *reinterpret_cast<uint2*>(&sBlo[row * SSTR + c * 4]) =
                __ldg(reinterpret_cast<const uint2*>(
                    g_Wlo + (size_t)(bn + row) * IN_F + k0 + c * 4));
        }
        __syncthreads();

#pragma unroll
        for (int ks = 0; ks < 2; ks++) {
            uint32_t a[2][4], b[4][4];
            const uint32_t kOffA = (uint32_t)((ks * 16 + kA) * 2);
            const uint32_t kOffB = (uint32_t)((ks * 16 + kB) * 2);
#pragma unroll
            for (int am = 0; am < 2; am++)
                ldsm4(a[am], aHiB + (wm + am * 16 + rA) * (SSTR * 2) + kOffA);
#pragma unroll
            for (int nb = 0; nb < 4; nb++)
                ldsm4(b[nb], bHiB + (wn + nb * 16 + rB) * (SSTR * 2) + kOffB);
#pragma unroll
            for (int am = 0; am < 2; am++)
#pragma unroll
                for (int j = 0; j < 8; j++)
                    mma16816(acc[am][j], a[am], &b[j >> 1][(j & 1) * 2]);
#pragma unroll
            for (int nb = 0; nb < 4; nb++)
                ldsm4(b[nb], bLoB + (wn + nb * 16 + rB) * (SSTR * 2) + kOffB);
#pragma unroll
            for (int am = 0; am < 2; am++)
#pragma unroll
                for (int j = 0; j < 8; j++)
                    mma16816(acc[am][j], a[am], &b[j >> 1][(j & 1) * 2]);
#pragma unroll
            for (int am = 0; am < 2; am++)
                ldsm4(a[am], aLoB + (wm + am * 16 + rA) * (SSTR * 2) + kOffA);
#pragma unroll
            for (int nb = 0; nb < 4; nb++)
                ldsm4(b[nb], bHiB + (wn + nb * 16 + rB) * (SSTR * 2) + kOffB);
#pragma unroll
            for (int am = 0; am < 2; am++)
#pragma unroll
                for (int j = 0; j < 8; j++)
                    mma16816(acc[am][j], a[am], &b[j >> 1][(j & 1) * 2]);
        }
    }

    const int crow = lane >> 2, ccol = (lane & 3) * 2;
#pragma unroll
    for (int am = 0; am < 2; am++) {
#pragma unroll
        for (int j = 0; j < 8; j++) {
            int col = bn + wn + j * 8 + ccol;
            int r0  = bm + wm + am * 16 + crow;
            if (r0 < M) {
                *reinterpret_cast<float2*>(out + (size_t)r0 * OUTSTRIDE + col) =
                    make_float2(acc[am][j][0], acc[am][j][1]);
                *reinterpret_cast<__half2*>(g_ftH + (size_t)r0 * OUT_F + col) =
                    __floats2half2_rn(acc[am][j][0], acc[am][j][1]);
            }
            int r1 = r0 + 8;
            if (r1 < M) {
                *reinterpret_cast<float2*>(out + (size_t)r1 * OUTSTRIDE + col) =
                    make_float2(acc[am][j][2], acc[am][j][3]);
                *reinterpret_cast<__half2*>(g_ftH + (size_t)r1 * OUT_F + col) =
                    __floats2half2_rn(acc[am][j][2], acc[am][j][3]);
            }
        }
    }
}

// ---------------------------------------------------------------------------
// CSR scatter: one warp per dst node; fp16 gathers batched 8-wide so 8
// independent LDGs are in flight (MLP=8); fp32 accumulate; ONE plain
// STG.128 per node (also zeroes empty dst nodes).
// ---------------------------------------------------------------------------
__global__ __launch_bounds__(256)
void scatter_csr_kernel(float* out, int M, int colOff) {
    const int d    = (blockIdx.x * blockDim.x + threadIdx.x) >> 5;  // dst node
    const int lane = threadIdx.x & 31;
    if (d >= M) return;

    const int end   = g_offs[d];
    const int start = end - g_hist[d];

    const __half* ftb = g_ftH + colOff;
    float4 acc = make_float4(0.f, 0.f, 0.f, 0.f);

    for (int base = start; base < end; base += 32) {
        const int n = min(32, end - base);
        int2 rec;
        if (lane < n) rec = __ldg(&g_pack[base + lane]);
        int j = 0;
#pragma unroll 1
        for (; j + 8 <= n; j += 8) {
            uint2 raw[8];
            float vv[8];
#pragma unroll
            for (int q = 0; q < 8; q++) {
                int   s = __shfl_sync(0xffffffffu, rec.x, j + q);
                vv[q]   = __int_as_float(__shfl_sync(0xffffffffu, rec.y, j + q));
                raw[q]  = __ldg(reinterpret_cast<const uint2*>(
                                    ftb + (size_t)s * OUT_F) + lane);
            }
#pragma unroll
            for (int q = 0; q < 8; q++) {
                float2 f0 = __half22float2(*reinterpret_cast<__half2*>(&raw[q].x));
                float2 f1 = __half22float2(*reinterpret_cast<__half2*>(&raw[q].y));
                acc.x += vv[q] * f0.x;
                acc.y += vv[q] * f0.y;
                acc.z += vv[q] * f1.x;
                acc.w += vv[q] * f1.y;
            }
        }
        for (; j < n; j++) {
            int   s = __shfl_sync(0xffffffffu, rec.x, j);
            float v = __int_as_float(__shfl_sync(0xffffffffu, rec.y, j));
            uint2 raw = __ldg(reinterpret_cast<const uint2*>(
                                  ftb + (size_t)s * OUT_F) + lane);
            float2 f0 = __half22float2(*reinterpret_cast<__half2*>(&raw.x));
            float2 f1 = __half22float2(*reinterpret_cast<__half2*>(&raw.y));
            acc.x += v * f0.x;
            acc.y += v * f0.y;
            acc.z += v * f1.x;
            acc.w += v * f1.y;
        }
    }
    *reinterpret_cast<float4*>(out + (size_t)d * OUTSTRIDE + OUT_F + colOff +
                               lane * 4) = acc;
}

// ---------------------------------------------------------------------------
extern "C" void kernel_launch(void* const* d_in, const int* in_sizes, int n_in,
                              void* d_out, int out_size) {
    const float* input  = (const float*)d_in[0];   // [N, 256]
    const void*  esrc   = d_in[1];
    const void*  edst   = d_in[2];
    const float* evals  = (const float*)d_in[3];
    const float* weight = (const float*)d_in[4];   // [256, 256]
    float* out = (float*)d_out;                    // [N, 512]

    const int M = in_sizes[0] / IN_F;              // 100000
    const int E = in_sizes[1];                     // 3200000

    static cudaStream_t s1 = nullptr, s2 = nullptr;
    static cudaEvent_t evRoot, ev1, evG0, ev2;
    if (!s1) {   // one-time resource creation (not memory allocation)
        cudaStreamCreateWithFlags(&s1, cudaStreamNonBlocking);
        cudaStreamCreateWithFlags(&s2, cudaStreamNonBlocking);
        cudaEventCreateWithFlags(&evRoot, cudaEventDisableTiming);
        cudaEventCreateWithFlags(&ev1,    cudaEventDisableTiming);
        cudaEventCreateWithFlags(&evG0,   cudaEventDisableTiming);
        cudaEventCreateWithFlags(&ev2,    cudaEventDisableTiming);
    }

    // ---- fork side stream s1 for the sort chain ----
    cudaEventRecord(evRoot, 0);
    cudaStreamWaitEvent(s1, evRoot, 0);

    // s1: counting sort (independent of GEMM)
    zero_hist_kernel<<<NB / 256, 256, 0, s1>>>();
    detect_idx_kernel<<<1, 256, 0, s1>>>((const unsigned*)esrc);
    hist_kernel<<<(E + 255) / 256, 256, 0, s1>>>(edst, E);
    scanA_kernel<<<NB / 256, 256, 0, s1>>>();
    scanB_kernel<<<1, 512, 0, s1>>>();
    scanC_kernel<<<NB / 256, 256, 0, s1>>>();
    sort_pack_kernel<<<(E + 255) / 256, 256, 0, s1>>>(esrc, edst, evals, E);
    cudaEventRecord(ev1, s1);

    // s0 (capture stream): convert W, GEMM half 0 (cols 0-127)
    conv_w_kernel<<<(IN_F * OUT_F) / 256, 256>>>(weight);
    dim3 gg((M + 127) / 128, 1);
    gemm_mma_kernel<<<gg, 256>>>(input, out, M, 0);
    cudaEventRecord(evG0, 0);

    // s2: GEMM half 1 (cols 128-255), overlaps scatter pass 0
    cudaStreamWaitEvent(s2, evG0, 0);
    gemm_mma_kernel<<<gg, 256, 0, s2>>>(input, out, M, 128);
    cudaEventRecord(ev2, s2);

    // s0: scatter pass 0 (needs sort chain + gemm half 0)
    cudaStreamWaitEvent(0, ev1, 0);
    scatter_csr_kernel<<<(M + 7) / 8, 256>>>(out, M, 0);

    // s0: scatter pass 1 (needs gemm half 1)
    cudaStreamWaitEvent(0, ev2, 0);
    scatter_csr_kernel<<<(M + 7) / 8, 256>>>(out, M, 128);
}

// round 10
// speedup vs baseline: 1.4064x; 1.4064x over previous
#include <cuda_runtime.h>
#include <cuda_fp16.h>
#include <cstdint>

#define IN_F      256
#define OUT_F     256
#define OUTSTRIDE 512
#define MAXE      3200000
#define MAXM      100000
#define NB        100352          // 392 * 256 bins (>= N_NODES)

// ---------------- device scratch (allocation-free rule) ---------------------
__device__ __half        g_Wh[OUT_F * IN_F];    // fp16, transposed: [n][k]
__device__ __half        g_ftH[(size_t)MAXM * OUT_F];  // fp16 mirror of ft_input
__device__ int2          g_pack[MAXE];          // {src, val_bits}, sorted by dst
__device__ int           g_hist[NB];
__device__ int           g_offs[NB];
__device__ int           g_bsum[512];
__device__ unsigned      g_idx_is64;

// ---------------- helpers ---------------------------------------------------
static __device__ __forceinline__ uint32_t smem_u32(const void* p) {
    uint32_t a;
    asm("{ .reg .u64 t; cvta.to.shared.u64 t, %1; cvt.u32.u64 %0, t; }"
        : "=r"(a) : "l"(p));
    return a;
}
static __device__ __forceinline__ void ldsm4(uint32_t* r, uint32_t addr) {
    asm volatile("ldmatrix.sync.aligned.m8n8.x4.shared.b16 {%0,%1,%2,%3}, [%4];"
                 : "=r"(r[0]), "=r"(r[1]), "=r"(r[2]), "=r"(r[3]) : "r"(addr));
}
static __device__ __forceinline__ void mma16816f(float* c, const uint32_t* a,
                                                 const uint32_t* b) {
    asm volatile(
        "mma.sync.aligned.m16n8k16.row.col.f32.f16.f16.f32 "
        "{%0,%1,%2,%3}, {%4,%5,%6,%7}, {%8,%9}, {%0,%1,%2,%3};"
        : "+f"(c[0]), "+f"(c[1]), "+f"(c[2]), "+f"(c[3])
        : "r"(a[0]), "r"(a[1]), "r"(a[2]), "r"(a[3]), "r"(b[0]), "r"(b[1]));
}
// block-wide inclusive scan (blockDim multiple of 32, <= 1024)
static __device__ __forceinline__ int block_incl_scan(int v, int* shWarp) {
    const int lane = threadIdx.x & 31, w = threadIdx.x >> 5;
#pragma unroll
    for (int o = 1; o < 32; o <<= 1) {
        int t = __shfl_up_sync(0xffffffffu, v, o);
        if (lane >= o) v += t;
    }
    if (lane == 31) shWarp[w] = v;
    __syncthreads();
    if (w == 0) {
        const int nw = blockDim.x >> 5;
        int s = (lane < nw) ? shWarp[lane] : 0;
#pragma unroll
        for (int o = 1; o < 32; o <<= 1) {
            int t = __shfl_up_sync(0xffffffffu, s, o);
            if (lane >= o) s += t;
        }
        if (lane < nw) shWarp[lane] = s;
    }
    __syncthreads();
    if (w > 0) v += shWarp[w - 1];
    return v;
}

// ---------------------------------------------------------------------------
__global__ void detect_idx_kernel(const unsigned* __restrict__ p) {
    unsigned v = p[2 * threadIdx.x + 1];
    int any = __syncthreads_or(v != 0u);
    if (threadIdx.x == 0) g_idx_is64 = any ? 0u : 1u;
}

__global__ void zero_hist_kernel() {
    g_hist[blockIdx.x * 256 + threadIdx.x] = 0;
}

// W[k][n] -> transposed fp16: g_Wh[n][k].
__global__ void conv_w_kernel(const float* __restrict__ W) {
    int i = blockIdx.x * blockDim.x + threadIdx.x;   // 65536
    int k = i >> 8, n = i & 255;
    g_Wh[n * IN_F + k] = __float2half_rn(W[i]);
}

// ---------------------------------------------------------------------------
// Counting sort by dst: histogram -> scan -> scatter into 8B records.
// After sort_pack_kernel, g_offs[d] = END offset of d's run; start = end-hist.
// ---------------------------------------------------------------------------
__global__ void hist_kernel(const void* __restrict__ edst, int E) {
    int i = blockIdx.x * blockDim.x + threadIdx.x;
    if (i >= E) return;
    int d = g_idx_is64 ? (int)__ldg((const long long*)edst + i)
                       : __ldg((const int*)edst + i);
    atomicAdd(&g_hist[d], 1);
}
__global__ void scanA_kernel() {            // grid 392, block 256
    __shared__ int shW[8];
    int i = blockIdx.x * 256 + threadIdx.x;
    int v = g_hist[i];
    int inc = block_incl_scan(v, shW);
    g_offs[i] = inc - v;
    if (threadIdx.x == 255) g_bsum[blockIdx.x] = inc;
}
__global__ void scanB_kernel() {            // grid 1, block 512
    __shared__ int shW[16];
    int t = threadIdx.x;
    int v = (t < 392) ? g_bsum[t] : 0;
    int inc = block_incl_scan(v, shW);
    if (t < 392) g_bsum[t] = inc - v;
}
__global__ void scanC_kernel() {            // grid 392, block 256
    g_offs[blockIdx.x * 256 + threadIdx.x] += g_bsum[blockIdx.x];
}
__global__ void sort_pack_kernel(const void* __restrict__ esrc,
                                 const void* __restrict__ edst,
                                 const float* __restrict__ ev, int E) {
    int i = blockIdx.x * blockDim.x + threadIdx.x;
    if (i >= E) return;
    int s, d;
    if (g_idx_is64) {
        s = (int)__ldg((const long long*)esrc + i);
        d = (int)__ldg((const long long*)edst + i);
    } else {
        s = __ldg((const int*)esrc + i);
        d = __ldg((const int*)edst + i);
    }
    int pos = atomicAdd(&g_offs[d], 1);
    g_pack[pos] = make_int2(s, __float_as_int(__ldg(ev + i)));
}

// ---------------------------------------------------------------------------
// GEMM via mma.sync (HMMA.16816 fp16, fp32 accum), single product.
// Block 128x128, 8 warps (warp tile 32x64), K-chunk 32, K=256.
// bnBase selects the N-half. Epilogue writes fp32 out AND fp16 mirror g_ftH.
// ---------------------------------------------------------------------------
#define SSTR 40

__global__ __launch_bounds__(256)
void gemm_mma_kernel(const float* __restrict__ X, float* __restrict__ out,
                     int M, int bnBase) {
    __shared__ __align__(16) __half sA[128 * SSTR];
    __shared__ __align__(16) __half sB[128 * SSTR];

    const int tid  = threadIdx.x;
    const int lane = tid & 31, wid = tid >> 5;
    const int bm = blockIdx.x * 128;
    const int bn = bnBase;
    const int wm = (wid & 3) * 32;
    const int wn = (wid >> 2) * 64;

    float acc[2][8][4];
#pragma unroll
    for (int i = 0; i < 2; i++)
#pragma unroll
        for (int j = 0; j < 8; j++)
#pragma unroll
            for (int k = 0; k < 4; k++) acc[i][j][k] = 0.f;

    const int rA = ((lane >> 3) & 1) * 8 + (lane & 7);
    const int kA = (lane >> 4) * 8;
    const int rB = (lane >> 4) * 8 + (lane & 7);
    const int kB = ((lane >> 3) & 1) * 8;

    const uint32_t aB = smem_u32(sA), bB = smem_u32(sB);

    for (int kc = 0; kc < 8; kc++) {
        const int k0 = kc * 32;
        __syncthreads();
        // A fill: fp32 -> fp16
#pragma unroll
        for (int i = 0; i < 4; i++) {
            int idx = tid + i * 256;
            int row = idx >> 3, c = idx & 7;
            float4 v = make_float4(0.f, 0.f, 0.f, 0.f);
            if (bm + row < M)
                v = __ldg(reinterpret_cast<const float4*>(
                        X + (size_t)(bm + row) * IN_F + k0 + c * 4));
            __half2 h01 = __floats2half2_rn(v.x, v.y);
            __half2 h23 = __floats2half2_rn(v.z, v.w);
            uint2 ph;
            ph.x = *reinterpret_cast<uint32_t*>(&h01);
            ph.y = *reinterpret_cast<uint32_t*>(&h23);
            *reinterpret_cast<uint2*>(&sA[row * SSTR + c * 4]) = ph;
        }
        // B fill: fp16 straight copy
#pragma unroll
        for (int i = 0; i < 4; i++) {
            int idx = tid + i * 256;
            int row = idx >> 3, c = idx & 7;
            *reinterpret_cast<uint2*>(&sB[row * SSTR + c * 4]) =
                __ldg(reinterpret_cast<const uint2*>(
                    g_Wh + (size_t)(bn + row) * IN_F + k0 + c * 4));
        }
        __syncthreads();

#pragma unroll
        for (int ks = 0; ks < 2; ks++) {
            uint32_t a[2][4], b[4][4];
            const uint32_t kOffA = (uint32_t)((ks * 16 + kA) * 2);
            const uint32_t kOffB = (uint32_t)((ks * 16 + kB) * 2);
#pragma unroll
            for (int am = 0; am < 2; am++)
                ldsm4(a[am], aB + (wm + am * 16 + rA) * (SSTR * 2) + kOffA);
#pragma unroll
            for (int nb = 0; nb < 4; nb++)
                ldsm4(b[nb], bB + (wn + nb * 16 + rB) * (SSTR * 2) + kOffB);
#pragma unroll
            for (int am = 0; am < 2; am++)
#pragma unroll
                for (int j = 0; j < 8; j++)
                    mma16816f(acc[am][j], a[am], &b[j >> 1][(j & 1) * 2]);
        }
    }

    const int crow = lane >> 2, ccol = (lane & 3) * 2;
#pragma unroll
    for (int am = 0; am < 2; am++) {
#pragma unroll
        for (int j = 0; j < 8; j++) {
            int col = bn + wn + j * 8 + ccol;
            int r0  = bm + wm + am * 16 + crow;
            if (r0 < M) {
                *reinterpret_cast<float2*>(out + (size_t)r0 * OUTSTRIDE + col) =
                    make_float2(acc[am][j][0], acc[am][j][1]);
                *reinterpret_cast<__half2*>(g_ftH + (size_t)r0 * OUT_F + col) =
                    __floats2half2_rn(acc[am][j][0], acc[am][j][1]);
            }
            int r1 = r0 + 8;
            if (r1 < M) {
                *reinterpret_cast<float2*>(out + (size_t)r1 * OUTSTRIDE + col) =
                    make_float2(acc[am][j][2], acc[am][j][3]);
                *reinterpret_cast<__half2*>(g_ftH + (size_t)r1 * OUT_F + col) =
                    __floats2half2_rn(acc[am][j][2], acc[am][j][3]);
            }
        }
    }
}

// ---------------------------------------------------------------------------
// CSR scatter (round-8 form): one warp per dst node; fp16 gathers; fp32
// accumulate; ONE plain STG.128 per node (also zeroes empty dst nodes).
// ---------------------------------------------------------------------------
__global__ __launch_bounds__(256)
void scatter_csr_kernel(float* out, int M, int colOff) {
    const int d    = (blockIdx.x * blockDim.x + threadIdx.x) >> 5;  // dst node
    const int lane = threadIdx.x & 31;
    if (d >= M) return;

    const int end   = g_offs[d];
    const int start = end - g_hist[d];

    const __half* ftb = g_ftH + colOff;
    float4 acc = make_float4(0.f, 0.f, 0.f, 0.f);

    for (int base = start; base < end; base += 32) {
        const int n = min(32, end - base);
        int2 rec;
        if (lane < n) rec = __ldg(&g_pack[base + lane]);
        for (int j = 0; j < n; j++) {
            int   s = __shfl_sync(0xffffffffu, rec.x, j);
            float v = __int_as_float(__shfl_sync(0xffffffffu, rec.y, j));
            uint2 raw = __ldg(reinterpret_cast<const uint2*>(
                                  ftb + (size_t)s * OUT_F) + lane);
            float2 f0 = __half22float2(*reinterpret_cast<__half2*>(&raw.x));
            float2 f1 = __half22float2(*reinterpret_cast<__half2*>(&raw.y));
            acc.x += v * f0.x;
            acc.y += v * f0.y;
            acc.z += v * f1.x;
            acc.w += v * f1.y;
        }
    }
    *reinterpret_cast<float4*>(out + (size_t)d * OUTSTRIDE + OUT_F + colOff +
                               lane * 4) = acc;
}

// ---------------------------------------------------------------------------
extern "C" void kernel_launch(void* const* d_in, const int* in_sizes, int n_in,
                              void* d_out, int out_size) {
    const float* input  = (const float*)d_in[0];   // [N, 256]
    const void*  esrc   = d_in[1];
    const void*  edst   = d_in[2];
    const float* evals  = (const float*)d_in[3];
    const float* weight = (const float*)d_in[4];   // [256, 256]
    float* out = (float*)d_out;                    // [N, 512]

    const int M = in_sizes[0] / IN_F;              // 100000
    const int E = in_sizes[1];                     // 3200000

    static cudaStream_t s1 = nullptr, s2 = nullptr;
    static cudaEvent_t evRoot, ev1, evG0, ev2;
    if (!s1) {   // one-time resource creation (not memory allocation)
        cudaStreamCreateWithFlags(&s1, cudaStreamNonBlocking);
        cudaStreamCreateWithFlags(&s2, cudaStreamNonBlocking);
        cudaEventCreateWithFlags(&evRoot, cudaEventDisableTiming);
        cudaEventCreateWithFlags(&ev1,    cudaEventDisableTiming);
        cudaEventCreateWithFlags(&evG0,   cudaEventDisableTiming);
        cudaEventCreateWithFlags(&ev2,    cudaEventDisableTiming);
    }

    // ---- fork side stream s1 for the sort chain ----
    cudaEventRecord(evRoot, 0);
    cudaStreamWaitEvent(s1, evRoot, 0);

    // s1: counting sort (independent of GEMM)
    zero_hist_kernel<<<NB / 256, 256, 0, s1>>>();
    detect_idx_kernel<<<1, 256, 0, s1>>>((const unsigned*)esrc);
    hist_kernel<<<(E + 255) / 256, 256, 0, s1>>>(edst, E);
    scanA_kernel<<<NB / 256, 256, 0, s1>>>();
    scanB_kernel<<<1, 512, 0, s1>>>();
    scanC_kernel<<<NB / 256, 256, 0, s1>>>();
    sort_pack_kernel<<<(E + 255) / 256, 256, 0, s1>>>(esrc, edst, evals, E);
    cudaEventRecord(ev1, s1);

    // s0 (capture stream): convert W, GEMM half 0 (cols 0-127)
    conv_w_kernel<<<(IN_F * OUT_F) / 256, 256>>>(weight);
    dim3 gg((M + 127) / 128, 1);
    gemm_mma_kernel<<<gg, 256>>>(input, out, M, 0);
    cudaEventRecord(evG0, 0);

    // s2: GEMM half 1 (cols 128-255), overlaps scatter pass 0
    cudaStreamWaitEvent(s2, evG0, 0);
    gemm_mma_kernel<<<gg, 256, 0, s2>>>(input, out, M, 128);
    cudaEventRecord(ev2, s2);

    // s0: scatter pass 0 (needs sort chain + gemm half 0)
    cudaStreamWaitEvent(0, ev1, 0);
    scatter_csr_kernel<<<(M + 7) / 8, 256>>>(out, M, 0);

    // s0: scatter pass 1 (needs gemm half 1)
    cudaStreamWaitEvent(0, ev2, 0);
    scatter_csr_kernel<<<(M + 7) / 8, 256>>>(out, M, 128);
}

// round 12
// speedup vs baseline: 1.4066x; 1.0001x over previous
#include <cuda_runtime.h>
#include <cuda_fp16.h>
#include <cstdint>

#define IN_F      256
#define OUT_F     256
#define OUTSTRIDE 512
#define MAXE      3200000
#define MAXM      100000
#define NB        100352          // 392 * 256 bins (>= N_NODES)

// ---------------- device scratch (allocation-free rule) ---------------------
__device__ __half        g_Wh[OUT_F * IN_F];    // fp16, transposed: [n][k]
__device__ __half        g_ftH[(size_t)MAXM * OUT_F];  // fp16 mirror of ft_input
__device__ int2          g_pack[MAXE];          // {src, val_bits}, sorted by dst
__device__ int           g_hist[NB];
__device__ int           g_offs[NB];
__device__ int           g_bsum[512];
__device__ unsigned      g_idx_is64;

// ---------------- helpers ---------------------------------------------------
static __device__ __forceinline__ uint32_t smem_u32(const void* p) {
    uint32_t a;
    asm("{ .reg .u64 t; cvta.to.shared.u64 t, %1; cvt.u32.u64 %0, t; }"
        : "=r"(a) : "l"(p));
    return a;
}
static __device__ __forceinline__ void ldsm4(uint32_t* r, uint32_t addr) {
    asm volatile("ldmatrix.sync.aligned.m8n8.x4.shared.b16 {%0,%1,%2,%3}, [%4];"
                 : "=r"(r[0]), "=r"(r[1]), "=r"(r[2]), "=r"(r[3]) : "r"(addr));
}
static __device__ __forceinline__ void mma16816f(float* c, const uint32_t* a,
                                                 const uint32_t* b) {
    asm volatile(
        "mma.sync.aligned.m16n8k16.row.col.f32.f16.f16.f32 "
        "{%0,%1,%2,%3}, {%4,%5,%6,%7}, {%8,%9}, {%0,%1,%2,%3};"
        : "+f"(c[0]), "+f"(c[1]), "+f"(c[2]), "+f"(c[3])
        : "r"(a[0]), "r"(a[1]), "r"(a[2]), "r"(a[3]), "r"(b[0]), "r"(b[1]));
}
// block-wide inclusive scan (blockDim multiple of 32, <= 1024)
static __device__ __forceinline__ int block_incl_scan(int v, int* shWarp) {
    const int lane = threadIdx.x & 31, w = threadIdx.x >> 5;
#pragma unroll
    for (int o = 1; o < 32; o <<= 1) {
        int t = __shfl_up_sync(0xffffffffu, v, o);
        if (lane >= o) v += t;
    }
    if (lane == 31) shWarp[w] = v;
    __syncthreads();
    if (w == 0) {
        const int nw = blockDim.x >> 5;
        int s = (lane < nw) ? shWarp[lane] : 0;
#pragma unroll
        for (int o = 1; o < 32; o <<= 1) {
            int t = __shfl_up_sync(0xffffffffu, s, o);
            if (lane >= o) s += t;
        }
        if (lane < nw) shWarp[lane] = s;
    }
    __syncthreads();
    if (w > 0) v += shWarp[w - 1];
    return v;
}

// ---------------------------------------------------------------------------
__global__ void detect_idx_kernel(const unsigned* __restrict__ p) {
    unsigned v = p[2 * threadIdx.x + 1];
    int any = __syncthreads_or(v != 0u);
    if (threadIdx.x == 0) g_idx_is64 = any ? 0u : 1u;
}

__global__ void zero_hist_kernel() {
    g_hist[blockIdx.x * 256 + threadIdx.x] = 0;
}

// W[k][n] -> transposed fp16: g_Wh[n][k].
__global__ void conv_w_kernel(const float* __restrict__ W) {
    int i = blockIdx.x * blockDim.x + threadIdx.x;   // 65536
    int k = i >> 8, n = i & 255;
    g_Wh[n * IN_F + k] = __float2half_rn(W[i]);
}

// ---------------------------------------------------------------------------
// Counting sort by dst: histogram -> scan -> scatter into 8B records.
// After sort_pack_kernel, g_offs[d] = END offset of d's run; start = end-hist.
// ---------------------------------------------------------------------------
__global__ void hist_kernel(const void* __restrict__ edst, int E) {
    int i = blockIdx.x * blockDim.x + threadIdx.x;
    if (i >= E) return;
    int d = g_idx_is64 ? (int)__ldg((const long long*)edst + i)
                       : __ldg((const int*)edst + i);
    atomicAdd(&g_hist[d], 1);
}
__global__ void scanA_kernel() {            // grid 392, block 256
    __shared__ int shW[8];
    int i = blockIdx.x * 256 + threadIdx.x;
    int v = g_hist[i];
    int inc = block_incl_scan(v, shW);
    g_offs[i] = inc - v;
    if (threadIdx.x == 255) g_bsum[blockIdx.x] = inc;
}
__global__ void scanB_kernel() {            // grid 1, block 512
    __shared__ int shW[16];
    int t = threadIdx.x;
    int v = (t < 392) ? g_bsum[t] : 0;
    int inc = block_incl_scan(v, shW);
    if (t < 392) g_bsum[t] = inc - v;
}
__global__ void scanC_kernel() {            // grid 392, block 256
    g_offs[blockIdx.x * 256 + threadIdx.x] += g_bsum[blockIdx.x];
}
__global__ void sort_pack_kernel(const void* __restrict__ esrc,
                                 const void* __restrict__ edst,
                                 const float* __restrict__ ev, int E) {
    int i = blockIdx.x * blockDim.x + threadIdx.x;
    if (i >= E) return;
    int s, d;
    if (g_idx_is64) {
        s = (int)__ldg((const long long*)esrc + i);
        d = (int)__ldg((const long long*)edst + i);
    } else {
        s = __ldg((const int*)esrc + i);
        d = __ldg((const int*)edst + i);
    }
    int pos = atomicAdd(&g_offs[d], 1);
    g_pack[pos] = make_int2(s, __float_as_int(__ldg(ev + i)));
}

// ---------------------------------------------------------------------------
// GEMM via mma.sync (HMMA.16816 fp16, fp32 accum), single product.
// Block 128x128, 8 warps (warp tile 32x64), K-chunk 32, K=256.
// bnBase selects the N-half. Epilogue writes fp32 out AND fp16 mirror g_ftH.
// ---------------------------------------------------------------------------
#define SSTR 40

__global__ __launch_bounds__(256)
void gemm_mma_kernel(const float* __restrict__ X, float* __restrict__ out,
                     int M, int bnBase) {
    __shared__ __align__(16) __half sA[128 * SSTR];
    __shared__ __align__(16) __half sB[128 * SSTR];

    const int tid  = threadIdx.x;
    const int lane = tid & 31, wid = tid >> 5;
    const int bm = blockIdx.x * 128;
    const int bn = bnBase;
    const int wm = (wid & 3) * 32;
    const int wn = (wid >> 2) * 64;

    float acc[2][8][4];
#pragma unroll
    for (int i = 0; i < 2; i++)
#pragma unroll
        for (int j = 0; j < 8; j++)
#pragma unroll
            for (int k = 0; k < 4; k++) acc[i][j][k] = 0.f;

    const int rA = ((lane >> 3) & 1) * 8 + (lane & 7);
    const int kA = (lane >> 4) * 8;
    const int rB = (lane >> 4) * 8 + (lane & 7);
    const int kB = ((lane >> 3) & 1) * 8;

    const uint32_t aB = smem_u32(sA), bB = smem_u32(sB);

    for (int kc = 0; kc < 8; kc++) {
        const int k0 = kc * 32;
        __syncthreads();
        // A fill: fp32 -> fp16
#pragma unroll
        for (int i = 0; i < 4; i++) {
            int idx = tid + i * 256;
            int row = idx >> 3, c = idx & 7;
            float4 v = make_float4(0.f, 0.f, 0.f, 0.f);
            if (bm + row < M)
                v = __ldg(reinterpret_cast<const float4*>(
                        X + (size_t)(bm + row) * IN_F + k0 + c * 4));
            __half2 h01 = __floats2half2_rn(v.x, v.y);
            __half2 h23 = __floats2half2_rn(v.z, v.w);
            uint2 ph;
            ph.x = *reinterpret_cast<uint32_t*>(&h01);
            ph.y = *reinterpret_cast<uint32_t*>(&h23);
            *reinterpret_cast<uint2*>(&sA[row * SSTR + c * 4]) = ph;
        }
        // B fill: fp16 straight copy
#pragma unroll
        for (int i = 0; i < 4; i++) {
            int idx = tid + i * 256;
            int row = idx >> 3, c = idx & 7;
            *reinterpret_cast<uint2*>(&sB[row * SSTR + c * 4]) =
                __ldg(reinterpret_cast<const uint2*>(
                    g_Wh + (size_t)(bn + row) * IN_F + k0 + c * 4));
        }
        __syncthreads();

#pragma unroll
        for (int ks = 0; ks < 2; ks++) {
            uint32_t a[2][4], b[4][4];
            const uint32_t kOffA = (uint32_t)((ks * 16 + kA) * 2);
            const uint32_t kOffB = (uint32_t)((ks * 16 + kB) * 2);
#pragma unroll
            for (int am = 0; am < 2; am++)
                ldsm4(a[am], aB + (wm + am * 16 + rA) * (SSTR * 2) + kOffA);
#pragma unroll
            for (int nb = 0; nb < 4; nb++)
                ldsm4(b[nb], bB + (wn + nb * 16 + rB) * (SSTR * 2) + kOffB);
#pragma unroll
            for (int am = 0; am < 2; am++)
#pragma unroll
                for (int j = 0; j < 8; j++)
                    mma16816f(acc[am][j], a[am], &b[j >> 1][(j & 1) * 2]);
        }
    }

    const int crow = lane >> 2, ccol = (lane & 3) * 2;
#pragma unroll
    for (int am = 0; am < 2; am++) {
#pragma unroll
        for (int j = 0; j < 8; j++) {
            int col = bn + wn + j * 8 + ccol;
            int r0  = bm + wm + am * 16 + crow;
            if (r0 < M) {
                *reinterpret_cast<float2*>(out + (size_t)r0 * OUTSTRIDE + col) =
                    make_float2(acc[am][j][0], acc[am][j][1]);
                *reinterpret_cast<__half2*>(g_ftH + (size_t)r0 * OUT_F + col) =
                    __floats2half2_rn(acc[am][j][0], acc[am][j][1]);
            }
            int r1 = r0 + 8;
            if (r1 < M) {
                *reinterpret_cast<float2*>(out + (size_t)r1 * OUTSTRIDE + col) =
                    make_float2(acc[am][j][2], acc[am][j][3]);
                *reinterpret_cast<__half2*>(g_ftH + (size_t)r1 * OUT_F + col) =
                    __floats2half2_rn(acc[am][j][2], acc[am][j][3]);
            }
        }
    }
}

// ---------------------------------------------------------------------------
// CSR scatter: one warp per dst node; fp16 gathers; fp32 accumulate; ONE
// plain STG.128 per node (also zeroes empty dst nodes). The two passes
// (colOff 0 / 128) touch disjoint data and run CONCURRENTLY on two streams.
// ---------------------------------------------------------------------------
__global__ __launch_bounds__(256)
void scatter_csr_kernel(float* out, int M, int colOff) {
    const int d    = (blockIdx.x * blockDim.x + threadIdx.x) >> 5;  // dst node
    const int lane = threadIdx.x & 31;
    if (d >= M) return;

    const int end   = g_offs[d];
    const int start = end - g_hist[d];

    const __half* ftb = g_ftH + colOff;
    float4 acc = make_float4(0.f, 0.f, 0.f, 0.f);

    for (int base = start; base < end; base += 32) {
        const int n = min(32, end - base);
        int2 rec;
        if (lane < n) rec = __ldg(&g_pack[base + lane]);
        for (int j = 0; j < n; j++) {
            int   s = __shfl_sync(0xffffffffu, rec.x, j);
            float v = __int_as_float(__shfl_sync(0xffffffffu, rec.y, j));
            uint2 raw = __ldg(reinterpret_cast<const uint2*>(
                                  ftb + (size_t)s * OUT_F) + lane);
            float2 f0 = __half22float2(*reinterpret_cast<__half2*>(&raw.x));
            float2 f1 = __half22float2(*reinterpret_cast<__half2*>(&raw.y));
            acc.x += v * f0.x;
            acc.y += v * f0.y;
            acc.z += v * f1.x;
            acc.w += v * f1.y;
        }
    }
    *reinterpret_cast<float4*>(out + (size_t)d * OUTSTRIDE + OUT_F + colOff +
                               lane * 4) = acc;
}

// trivial join helper (gives s0 a terminal node after the cross-stream wait)
__global__ void join_kernel() {}

// ---------------------------------------------------------------------------
extern "C" void kernel_launch(void* const* d_in, const int* in_sizes, int n_in,
                              void* d_out, int out_size) {
    const float* input  = (const float*)d_in[0];   // [N, 256]
    const void*  esrc   = d_in[1];
    const void*  edst   = d_in[2];
    const float* evals  = (const float*)d_in[3];
    const float* weight = (const float*)d_in[4];   // [256, 256]
    float* out = (float*)d_out;                    // [N, 512]

    const int M = in_sizes[0] / IN_F;              // 100000
    const int E = in_sizes[1];                     // 3200000

    static cudaStream_t s1 = nullptr, s2 = nullptr;
    static cudaEvent_t evRoot, ev1, evC, ev2;
    if (!s1) {   // one-time resource creation (not memory allocation)
        cudaStreamCreateWithFlags(&s1, cudaStreamNonBlocking);
        cudaStreamCreateWithFlags(&s2, cudaStreamNonBlocking);
        cudaEventCreateWithFlags(&evRoot, cudaEventDisableTiming);
        cudaEventCreateWithFlags(&ev1,    cudaEventDisableTiming);
        cudaEventCreateWithFlags(&evC,    cudaEventDisableTiming);
        cudaEventCreateWithFlags(&ev2,    cudaEventDisableTiming);
    }

    // ---- fork side stream s1 for the sort chain ----
    cudaEventRecord(evRoot, 0);
    cudaStreamWaitEvent(s1, evRoot, 0);

    // s1: counting sort (independent of GEMM)
    zero_hist_kernel<<<NB / 256, 256, 0, s1>>>();
    detect_idx_kernel<<<1, 256, 0, s1>>>((const unsigned*)esrc);
    hist_kernel<<<(E + 255) / 256, 256, 0, s1>>>(edst, E);
    scanA_kernel<<<NB / 256, 256, 0, s1>>>();
    scanB_kernel<<<1, 512, 0, s1>>>();
    scanC_kernel<<<NB / 256, 256, 0, s1>>>();
    sort_pack_kernel<<<(E + 255) / 256, 256, 0, s1>>>(esrc, edst, evals, E);
    cudaEventRecord(ev1, s1);

    // s0: convert W -> evC
    conv_w_kernel<<<(IN_F * OUT_F) / 256, 256>>>(weight);
    cudaEventRecord(evC, 0);

    // s2: GEMM half 1 (cols 128-255) right after conv_w, then scatter pass 1
    cudaStreamWaitEvent(s2, evC, 0);
    dim3 gg((M + 127) / 128, 1);
    gemm_mma_kernel<<<gg, 256, 0, s2>>>(input, out, M, 128);
    cudaStreamWaitEvent(s2, ev1, 0);
    scatter_csr_kernel<<<(M + 7) / 8, 256, 0, s2>>>(out, M, 128);
    cudaEventRecord(ev2, s2);

    // s0: GEMM half 0 (cols 0-127), then scatter pass 0 (concurrent with s2's)
    gemm_mma_kernel<<<gg, 256>>>(input, out, M, 0);
    cudaStreamWaitEvent(0, ev1, 0);
    scatter_csr_kernel<<<(M + 7) / 8, 256>>>(out, M, 0);

    // join s2 into s0 so the graph's terminal depends on both scatters
    cudaStreamWaitEvent(0, ev2, 0);
    join_kernel<<<1, 32>>>();
}

// round 13
// speedup vs baseline: 1.5980x; 1.1361x over previous
#include <cuda_runtime.h>
#include <cuda_fp16.h>
#include <cstdint>

#define IN_F      256
#define OUT_F     256
#define OUTSTRIDE 512
#define MAXE      3200000
#define MAXM      100000
#define NB        100352          // >= N_NODES, multiple of 256
#define SLOT_CAP  64              // Poisson(32) tail beyond 64 ~ 4e-7
#define SPILL_MAX 65536

// ---------------- device scratch (allocation-free rule) ---------------------
__device__ __half        g_Wh[OUT_F * IN_F];    // fp16, transposed: [n][k]
__device__ __half        g_ftH[(size_t)MAXM * OUT_F];  // fp16 mirror of ft_input
__device__ int2          g_slots[(size_t)NB * SLOT_CAP]; // {src, val_bits} per dst
__device__ int           g_cnt[NB];
__device__ int4          g_spill[SPILL_MAX];    // {src, dst, val_bits, 0}
__device__ int           g_spill_cnt;
__device__ unsigned      g_idx_is64;

// ---------------- helpers ---------------------------------------------------
static __device__ __forceinline__ uint32_t smem_u32(const void* p) {
    uint32_t a;
    asm("{ .reg .u64 t; cvta.to.shared.u64 t, %1; cvt.u32.u64 %0, t; }"
        : "=r"(a) : "l"(p));
    return a;
}
static __device__ __forceinline__ void ldsm4(uint32_t* r, uint32_t addr) {
    asm volatile("ldmatrix.sync.aligned.m8n8.x4.shared.b16 {%0,%1,%2,%3}, [%4];"
                 : "=r"(r[0]), "=r"(r[1]), "=r"(r[2]), "=r"(r[3]) : "r"(addr));
}
static __device__ __forceinline__ void mma16816f(float* c, const uint32_t* a,
                                                 const uint32_t* b) {
    asm volatile(
        "mma.sync.aligned.m16n8k16.row.col.f32.f16.f16.f32 "
        "{%0,%1,%2,%3}, {%4,%5,%6,%7}, {%8,%9}, {%0,%1,%2,%3};"
        : "+f"(c[0]), "+f"(c[1]), "+f"(c[2]), "+f"(c[3])
        : "r"(a[0]), "r"(a[1]), "r"(a[2]), "r"(a[3]), "r"(b[0]), "r"(b[1]));
}

// ---------------------------------------------------------------------------
__global__ void detect_idx_kernel(const unsigned* __restrict__ p) {
    unsigned v = p[2 * threadIdx.x + 1];
    int any = __syncthreads_or(v != 0u);
    if (threadIdx.x == 0) g_idx_is64 = any ? 0u : 1u;
}

__global__ void zero_cnt_kernel() {
    int i = blockIdx.x * 256 + threadIdx.x;
    g_cnt[i] = 0;
    if (i == 0) g_spill_cnt = 0;
}

// W[k][n] -> transposed fp16: g_Wh[n][k].
__global__ void conv_w_kernel(const float* __restrict__ W) {
    int i = blockIdx.x * blockDim.x + threadIdx.x;   // 65536
    int k = i >> 8, n = i & 255;
    g_Wh[n * IN_F + k] = __float2half_rn(W[i]);
}

// ---------------------------------------------------------------------------
// Direct bucketing: one fused pass replaces hist+scan+sort. Each edge grabs a
// slot in its dst's fixed-capacity bucket; rare overflow goes to spill list.
// ---------------------------------------------------------------------------
__global__ void bucket_kernel(const void* __restrict__ esrc,
                              const void* __restrict__ edst,
                              const float* __restrict__ ev, int E) {
    int i = blockIdx.x * blockDim.x + threadIdx.x;
    if (i >= E) return;
    int s, d;
    if (g_idx_is64) {
        s = (int)__ldg((const long long*)esrc + i);
        d = (int)__ldg((const long long*)edst + i);
    } else {
        s = __ldg((const int*)esrc + i);
        d = __ldg((const int*)edst + i);
    }
    int vb = __float_as_int(__ldg(ev + i));
    int pos = atomicAdd(&g_cnt[d], 1);
    if (pos < SLOT_CAP) {
        g_slots[(size_t)d * SLOT_CAP + pos] = make_int2(s, vb);
    } else {
        int sp = atomicAdd(&g_spill_cnt, 1);
        if (sp < SPILL_MAX) g_spill[sp] = make_int4(s, d, vb, 0);
    }
}

// ---------------------------------------------------------------------------
// GEMM via mma.sync (HMMA.16816 fp16, fp32 accum), single product.
// Block 128x128, 8 warps (warp tile 32x64), K-chunk 32, K=256.
// bnBase selects the N-half. Epilogue writes fp32 out AND fp16 mirror g_ftH.
// ---------------------------------------------------------------------------
#define SSTR 40

__global__ __launch_bounds__(256)
void gemm_mma_kernel(const float* __restrict__ X, float* __restrict__ out,
                     int M, int bnBase) {
    __shared__ __align__(16) __half sA[128 * SSTR];
    __shared__ __align__(16) __half sB[128 * SSTR];

    const int tid  = threadIdx.x;
    const int lane = tid & 31, wid = tid >> 5;
    const int bm = blockIdx.x * 128;
    const int bn = bnBase;
    const int wm = (wid & 3) * 32;
    const int wn = (wid >> 2) * 64;

    float acc[2][8][4];
#pragma unroll
    for (int i = 0; i < 2; i++)
#pragma unroll
        for (int j = 0; j < 8; j++)
#pragma unroll
            for (int k = 0; k < 4; k++) acc[i][j][k] = 0.f;

    const int rA = ((lane >> 3) & 1) * 8 + (lane & 7);
    const int kA = (lane >> 4) * 8;
    const int rB = (lane >> 4) * 8 + (lane & 7);
    const int kB = ((lane >> 3) & 1) * 8;

    const uint32_t aB = smem_u32(sA), bB = smem_u32(sB);

    for (int kc = 0; kc < 8; kc++) {
        const int k0 = kc * 32;
        __syncthreads();
        // A fill: fp32 -> fp16
#pragma unroll
        for (int i = 0; i < 4; i++) {
            int idx = tid + i * 256;
            int row = idx >> 3, c = idx & 7;
            float4 v = make_float4(0.f, 0.f, 0.f, 0.f);
            if (bm + row < M)
                v = __ldg(reinterpret_cast<const float4*>(
                        X + (size_t)(bm + row) * IN_F + k0 + c * 4));
            __half2 h01 = __floats2half2_rn(v.x, v.y);
            __half2 h23 = __floats2half2_rn(v.z, v.w);
            uint2 ph;
            ph.x = *reinterpret_cast<uint32_t*>(&h01);
            ph.y = *reinterpret_cast<uint32_t*>(&h23);
            *reinterpret_cast<uint2*>(&sA[row * SSTR + c * 4]) = ph;
        }
        // B fill: fp16 straight copy
#pragma unroll
        for (int i = 0; i < 4; i++) {
            int idx = tid + i * 256;
            int row = idx >> 3, c = idx & 7;
            *reinterpret_cast<uint2*>(&sB[row * SSTR + c * 4]) =
                __ldg(reinterpret_cast<const uint2*>(
                    g_Wh + (size_t)(bn + row) * IN_F + k0 + c * 4));
        }
        __syncthreads();

#pragma unroll
        for (int ks = 0; ks < 2; ks++) {
            uint32_t a[2][4], b[4][4];
            const uint32_t kOffA = (uint32_t)((ks * 16 + kA) * 2);
            const uint32_t kOffB = (uint32_t)((ks * 16 + kB) * 2);
#pragma unroll
            for (int am = 0; am < 2; am++)
                ldsm4(a[am], aB + (wm + am * 16 + rA) * (SSTR * 2) + kOffA);
#pragma unroll
            for (int nb = 0; nb < 4; nb++)
                ldsm4(b[nb], bB + (wn + nb * 16 + rB) * (SSTR * 2) + kOffB);
#pragma unroll
            for (int am = 0; am < 2; am++)
#pragma unroll
                for (int j = 0; j < 8; j++)
                    mma16816f(acc[am][j], a[am], &b[j >> 1][(j & 1) * 2]);
        }
    }

    const int crow = lane >> 2, ccol = (lane & 3) * 2;
#pragma unroll
    for (int am = 0; am < 2; am++) {
#pragma unroll
        for (int j = 0; j < 8; j++) {
            int col = bn + wn + j * 8 + ccol;
            int r0  = bm + wm + am * 16 + crow;
            if (r0 < M) {
                *reinterpret_cast<float2*>(out + (size_t)r0 * OUTSTRIDE + col) =
                    make_float2(acc[am][j][0], acc[am][j][1]);
                *reinterpret_cast<__half2*>(g_ftH + (size_t)r0 * OUT_F + col) =
                    __floats2half2_rn(acc[am][j][0], acc[am][j][1]);
            }
            int r1 = r0 + 8;
            if (r1 < M) {
                *reinterpret_cast<float2*>(out + (size_t)r1 * OUTSTRIDE + col) =
                    make_float2(acc[am][j][2], acc[am][j][3]);
                *reinterpret_cast<__half2*>(g_ftH + (size_t)r1 * OUT_F + col) =
                    __floats2half2_rn(acc[am][j][2], acc[am][j][3]);
            }
        }
    }
}

// ---------------------------------------------------------------------------
// Full-width scatter: one warp per dst node, all 256 features in one pass
// (lane -> 8 features). fp16 gathers, fp32 accumulate, two STG.128 per lane.
// Unconditional store also zeroes empty dst nodes.
// ---------------------------------------------------------------------------
__global__ __launch_bounds__(256)
void scatter_full_kernel(float* out, int M) {
    const int d    = (blockIdx.x * blockDim.x + threadIdx.x) >> 5;  // dst node
    const int lane = threadIdx.x & 31;
    if (d >= M) return;

    const int cnt = min(__ldg(&g_cnt[d]), SLOT_CAP);
    const int2* slots = g_slots + (size_t)d * SLOT_CAP;

    float4 a0 = make_float4(0.f, 0.f, 0.f, 0.f);
    float4 a1 = make_float4(0.f, 0.f, 0.f, 0.f);

    for (int base = 0; base < cnt; base += 32) {
        const int n = min(32, cnt - base);
        int2 rec;
        if (lane < n) rec = __ldg(&slots[base + lane]);
        for (int j = 0; j < n; j++) {
            int   s = __shfl_sync(0xffffffffu, rec.x, j);
            float v = __int_as_float(__shfl_sync(0xffffffffu, rec.y, j));
            uint4 raw = __ldg(reinterpret_cast<const uint4*>(
                                  g_ftH + (size_t)s * OUT_F) + lane);
            float2 f0 = __half22float2(*reinterpret_cast<__half2*>(&raw.x));
            float2 f1 = __half22float2(*reinterpret_cast<__half2*>(&raw.y));
            float2 f2 = __half22float2(*reinterpret_cast<__half2*>(&raw.z));
            float2 f3 = __half22float2(*reinterpret_cast<__half2*>(&raw.w));
            a0.x += v * f0.x;  a0.y += v * f0.y;
            a0.z += v * f1.x;  a0.w += v * f1.y;
            a1.x += v * f2.x;  a1.y += v * f2.y;
            a1.z += v * f3.x;  a1.w += v * f3.y;
        }
    }
    float* dst = out + (size_t)d * OUTSTRIDE + OUT_F + lane * 8;
    *reinterpret_cast<float4*>(dst)     = a0;
    *reinterpret_cast<float4*>(dst + 4) = a1;
}

// ---------------------------------------------------------------------------
// Spill cleanup: atomically add the (rare) overflow edges into the output.
// ---------------------------------------------------------------------------
__global__ void spill_kernel(float* out) {
    const int total  = min(g_spill_cnt, SPILL_MAX);
    const int lane   = threadIdx.x & 31;
    const int warpId = (blockIdx.x * blockDim.x + threadIdx.x) >> 5;
    const int nW     = (gridDim.x * blockDim.x) >> 5;

    for (int i = warpId; i < total; i += nW) {
        int4 r = g_spill[i];
        float v = __int_as_float(r.z);
        uint4 raw = __ldg(reinterpret_cast<const uint4*>(
                              g_ftH + (size_t)r.x * OUT_F) + lane);
        float2 f0 = __half22float2(*reinterpret_cast<__half2*>(&raw.x));
        float2 f1 = __half22float2(*reinterpret_cast<__half2*>(&raw.y));
        float2 f2 = __half22float2(*reinterpret_cast<__half2*>(&raw.z));
        float2 f3 = __half22float2(*reinterpret_cast<__half2*>(&raw.w));
        float* dp = out + (size_t)r.y * OUTSTRIDE + OUT_F + lane * 8;
        asm volatile("red.global.add.v4.f32 [%0], {%1,%2,%3,%4};"
                     :: "l"(dp), "f"(v * f0.x), "f"(v * f0.y),
                        "f"(v * f1.x), "f"(v * f1.y) : "memory");
        asm volatile("red.global.add.v4.f32 [%0], {%1,%2,%3,%4};"
                     :: "l"(dp + 4), "f"(v * f2.x), "f"(v * f2.y),
                        "f"(v * f3.x), "f"(v * f3.y) : "memory");
    }
}

// ---------------------------------------------------------------------------
extern "C" void kernel_launch(void* const* d_in, const int* in_sizes, int n_in,
                              void* d_out, int out_size) {
    const float* input  = (const float*)d_in[0];   // [N, 256]
    const void*  esrc   = d_in[1];
    const void*  edst   = d_in[2];
    const float* evals  = (const float*)d_in[3];
    const float* weight = (const float*)d_in[4];   // [256, 256]
    float* out = (float*)d_out;                    // [N, 512]

    const int M = in_sizes[0] / IN_F;              // 100000
    const int E = in_sizes[1];                     // 3200000

    static cudaStream_t s1 = nullptr, s2 = nullptr;
    static cudaEvent_t evRoot, ev1, evC, ev2;
    if (!s1) {   // one-time resource creation (not memory allocation)
        cudaStreamCreateWithFlags(&s1, cudaStreamNonBlocking);
        cudaStreamCreateWithFlags(&s2, cudaStreamNonBlocking);
        cudaEventCreateWithFlags(&evRoot, cudaEventDisableTiming);
        cudaEventCreateWithFlags(&ev1,    cudaEventDisableTiming);
        cudaEventCreateWithFlags(&evC,    cudaEventDisableTiming);
        cudaEventCreateWithFlags(&ev2,    cudaEventDisableTiming);
    }

    // ---- fork side stream s1 for the bucketing chain ----
    cudaEventRecord(evRoot, 0);
    cudaStreamWaitEvent(s1, evRoot, 0);

    // s1: direct bucketing (replaces hist + scans + sort)
    zero_cnt_kernel<<<NB / 256, 256, 0, s1>>>();
    detect_idx_kernel<<<1, 256, 0, s1>>>((const unsigned*)esrc);
    bucket_kernel<<<(E + 255) / 256, 256, 0, s1>>>(esrc, edst, evals, E);
    cudaEventRecord(ev1, s1);

    // s0: convert W -> evC
    conv_w_kernel<<<(IN_F * OUT_F) / 256, 256>>>(weight);
    cudaEventRecord(evC, 0);

    // s2: GEMM half 1 (cols 128-255) right after conv_w
    cudaStreamWaitEvent(s2, evC, 0);
    dim3 gg((M + 127) / 128, 1);
    gemm_mma_kernel<<<gg, 256, 0, s2>>>(input, out, M, 128);
    cudaEventRecord(ev2, s2);

    // s0: GEMM half 0 (cols 0-127)
    gemm_mma_kernel<<<gg, 256>>>(input, out, M, 0);

    // s0: full-width scatter (needs buckets + both GEMM halves), then spill fix
    cudaStreamWaitEvent(0, ev1, 0);
    cudaStreamWaitEvent(0, ev2, 0);
    scatter_full_kernel<<<(M + 7) / 8, 256>>>(out, M);
    spill_kernel<<<32, 256>>>(out);
}